// round 2
// baseline (speedup 1.0000x reference)
#include <cuda_runtime.h>

// Problem constants
#define NG 2048   // G
#define NB 32     // B (batch) -- one warp lane per b
#define NC 16     // C
#define NS 8      // S
#define NL 3      // L
#define NM 16     // m
#define FGAMMA 0.01f
#define FINVG  100.0f

// Scratch (device globals -- no allocation allowed)
__device__ float g_Rt[NG * NB];          // R, transposed: Rt[g*32 + b] (UN-normalized; scale held in g_max)
__device__ float g_Cv[NC * NG * NB];     // Cv_pre[(c*G+g)*32 + b]
__device__ float g_Hs[NG * NB];          // Hs_pre[g*32 + b]
__device__ float g_Ws[NM * NC];          // softmax(W) rows
__device__ int   g_max[16][8];           // banked float-bit maxes (all values >= 0)

// slot 3i = M1 (Cv max), 3i+1 = M2 (Hs max), 3i+2 = M3 (R max), i in [0,5); slot 15 = constant 1.0

__device__ __forceinline__ float get_scale(int slot) {
    int v = g_max[slot][0];
    #pragma unroll
    for (int k = 1; k < 8; k++) v = max(v, g_max[slot][k]);
    float m = __int_as_float(v);
    return (m > 1.0f) ? __fdividef(1.0f, m) : 1.0f;
}

__device__ __forceinline__ void block_max_atomic(float val, int slot) {
    int v = __float_as_int(val);  // valid ordering: all values non-negative
    #pragma unroll
    for (int o = 16; o > 0; o >>= 1) v = max(v, __shfl_xor_sync(0xffffffffu, v, o));
    __shared__ int s_red[8];
    if ((threadIdx.x & 31) == 0) s_red[threadIdx.x >> 5] = v;
    __syncthreads();
    if (threadIdx.x == 0) {
        int m = s_red[0];
        #pragma unroll
        for (int k = 1; k < 8; k++) m = max(m, s_red[k]);
        atomicMax(&g_max[slot][blockIdx.x & 7], m);
    }
}

// ---------------------------------------------------------------------------
// Init: transpose x -> Rt, compute Ws = softmax(W, axis=1), reset max slots.
// grid 256 x 256
__global__ void k_init(const float* __restrict__ x, const float* __restrict__ W) {
    int t = blockIdx.x * blockDim.x + threadIdx.x;
    int b = t >> 11;          // t = b*G + g
    int g = t & (NG - 1);
    g_Rt[g * NB + b] = x[t];

    if (blockIdx.x == 0) {
        if (threadIdx.x < NM) {   // softmax row m
            int m = threadIdx.x;
            float mx = -1e30f;
            #pragma unroll
            for (int c = 0; c < NC; c++) mx = fmaxf(mx, W[m * NC + c]);
            float e[NC]; float sum = 0.0f;
            #pragma unroll
            for (int c = 0; c < NC; c++) { e[c] = __expf(W[m * NC + c] - mx); sum += e[c]; }
            float inv = __fdividef(1.0f, sum);
            #pragma unroll
            for (int c = 0; c < NC; c++) g_Ws[m * NC + c] = e[c] * inv;
        }
        if (threadIdx.x >= 64 && threadIdx.x < 192) {   // reset 16*8 max banks
            int k = threadIdx.x - 64;
            ((int*)g_max)[k] = (k >= 15 * 8) ? __float_as_int(1.0f) : 0;  // slot 15 == 1.0
        }
    }
}

// ---------------------------------------------------------------------------
// K1: per (c,g) warp, lane = b.
//   body[s] = prod_l V[b, I[c,g,s,l]]   with V = Rt * sR
//   Cv_pre  = gamma * LSE_s(body/gamma);  atomicMax -> slotOut
// grid 4096 x 256 (32768 warps)
__global__ void k1_cv(const int* __restrict__ I, int slotR, int slotOut) {
    int tid  = blockIdx.x * blockDim.x + threadIdx.x;
    int warp = tid >> 5;          // cg = c*G + g   (matches I and Cv layouts)
    int lane = tid & 31;          // b

    float sR = get_scale(slotR);
    float s3 = sR * sR * sR;

    const int4* ip = reinterpret_cast<const int4*>(I) + warp * 6;  // 24 ints, 16B aligned
    int4 a0 = ip[0], a1 = ip[1], a2 = ip[2], a3 = ip[3], a4 = ip[4], a5 = ip[5];
    int idx[24] = { a0.x,a0.y,a0.z,a0.w, a1.x,a1.y,a1.z,a1.w, a2.x,a2.y,a2.z,a2.w,
                    a3.x,a3.y,a3.z,a3.w, a4.x,a4.y,a4.z,a4.w, a5.x,a5.y,a5.z,a5.w };

    float body[NS];
    #pragma unroll
    for (int s = 0; s < NS; s++) {
        float v0 = g_Rt[idx[3 * s + 0] * NB + lane];
        float v1 = g_Rt[idx[3 * s + 1] * NB + lane];
        float v2 = g_Rt[idx[3 * s + 2] * NB + lane];
        body[s] = v0 * v1 * v2 * s3;
    }

    float mx = body[0];
    #pragma unroll
    for (int s = 1; s < NS; s++) mx = fmaxf(mx, body[s]);
    float sum = 0.0f;
    #pragma unroll
    for (int s = 0; s < NS; s++) sum += __expf((body[s] - mx) * FINVG);
    float cv = fmaf(FGAMMA, __logf(sum), mx);

    g_Cv[warp * NB + lane] = cv;
    block_max_atomic(cv, slotOut);
}

// ---------------------------------------------------------------------------
// K2: per g warp, lane = b.
//   H[m] = sum_c Ws[m,c] * (Cv_pre[b,c,g] * s1);  Hs_pre = gamma*LSE_m(H/gamma)
// grid 256 x 256 (2048 warps)
__global__ void k2_h(int slotM1, int slotOut) {
    __shared__ float ws[NM * NC];
    ws[threadIdx.x] = g_Ws[threadIdx.x];
    __syncthreads();

    int tid  = blockIdx.x * blockDim.x + threadIdx.x;
    int g    = tid >> 5;
    int lane = tid & 31;   // b

    float s1 = get_scale(slotM1);

    float cv[NC];
    #pragma unroll
    for (int c = 0; c < NC; c++)
        cv[c] = g_Cv[(c * NG + g) * NB + lane] * s1;

    float h[NM];
    #pragma unroll
    for (int m = 0; m < NM; m++) {
        float acc = 0.0f;
        #pragma unroll
        for (int c = 0; c < NC; c++) acc = fmaf(ws[m * NC + c], cv[c], acc);
        h[m] = acc;
    }

    float mx = h[0];
    #pragma unroll
    for (int m = 1; m < NM; m++) mx = fmaxf(mx, h[m]);
    float sum = 0.0f;
    #pragma unroll
    for (int m = 0; m < NM; m++) sum += __expf((h[m] - mx) * FINVG);
    float hs = fmaf(FGAMMA, __logf(sum), mx);

    g_Hs[g * NB + lane] = hs;
    block_max_atomic(hs, slotOut);
}

// ---------------------------------------------------------------------------
// K3: elementwise softor of {R_old, Hs}: 2-way LSE, update R in place.
// grid 256 x 256 (65536 threads)
__global__ void k3_merge(int slotR, int slotM2, int slotOut) {
    int t = blockIdx.x * blockDim.x + threadIdx.x;
    float sR = get_scale(slotR);
    float s2 = get_scale(slotM2);

    float a  = g_Rt[t] * sR;
    float hv = g_Hs[t] * s2;
    float mx = fmaxf(a, hv);
    float mn = fminf(a, hv);
    float r  = fmaf(FGAMMA, __logf(1.0f + __expf((mn - mx) * FINVG)), mx);

    g_Rt[t] = r;
    block_max_atomic(r, slotOut);
}

// ---------------------------------------------------------------------------
// Output: apply final scale, transpose back to (B, G).
__global__ void k_out(float* __restrict__ out, int slotR) {
    int t = blockIdx.x * blockDim.x + threadIdx.x;  // t = b*G + g
    float s = get_scale(slotR);
    int b = t >> 11;
    int g = t & (NG - 1);
    out[t] = g_Rt[g * NB + b] * s;
}

// ---------------------------------------------------------------------------
extern "C" void kernel_launch(void* const* d_in, const int* in_sizes, int n_in,
                              void* d_out, int out_size) {
    const float* x = (const float*)d_in[0];   // (32, 2048) f32
    const float* W = (const float*)d_in[1];   // (16, 16) f32
    const int*   I = (const int*)  d_in[2];   // (16, 2048, 8, 3) i32
    float* out = (float*)d_out;               // (32, 2048) f32

    k_init<<<256, 256>>>(x, W);

    int slotR = 15;  // constant 1.0 (x is used unscaled in iteration 0)
    for (int i = 0; i < 5; i++) {
        k1_cv  <<<4096, 256>>>(I, slotR, 3 * i);
        k2_h   <<<256,  256>>>(3 * i, 3 * i + 1);
        k3_merge<<<256, 256>>>(slotR, 3 * i + 1, 3 * i + 2);
        slotR = 3 * i + 2;
    }

    k_out<<<256, 256>>>(out, slotR);
}